// round 14
// baseline (speedup 1.0000x reference)
#include <cuda_runtime.h>
#include <cuda_bf16.h>
#include <math.h>
#include <stdint.h>

#define TT 256
#define BB 256
#define FF 128
#define LL 3
#define HH 384
#define KKW 10
#define GG 1542
#define SS 64

#define NBLK 128        // 2 batch-halves x 64 col-slices
#define JC 6
#define NCOL 30
#define NT 4
#define XOS 33
#define NKK 24          // k16 chunks (384/16)
#define AFQ 6144        // uint4 per (parity,half): 24*8*32
#define SMEM_BYTES ((6144 + 128*XOS)*4)

// precompute mma kernel smem
#define PAST 68
#define PBST 132
#define GP 1664
#define PSMEM ((128*PAST + 64*PBST)*4)

static __device__ unsigned g_xkb[(size_t)TT * GG * BB / 2]; // bf16 [t][g][b]
static __device__ unsigned g_xp[(size_t)TT * (FF/2) * BB];
static __device__ unsigned g_wkp[GP * (FF/2)];
static __device__ uint4    g_haf[4 * AFQ];                  // [parity][half] A-fragment h
static __device__ float g_hist_h[KKW * BB * HH];
static __device__ float g_hist_d[KKW * BB];
static __device__ float g_dis[BB * KKW];
static __device__ float g_wh[KKW * BB * HH];
static __device__ float g_M[BB * HH];
static __device__ float g_P[BB * SS];
static __device__ float g_theme[BB * HH];
static __device__ float g_conv[BB * HH];
static __device__ float g_bias[GG];
static __device__ float g_wct[KKW * HH * HH];
static __device__ unsigned g_grp[8 * 32];                   // (half*4+g)*32, separate lines
static __device__ unsigned g_arrive;                        // flat root

__device__ __forceinline__ float sigmoidf(float x) { return 1.0f / (1.0f + expf(-x)); }
__device__ __forceinline__ float tanha(float x) {
    float y; asm("tanh.approx.f32 %0, %1;" : "=f"(y) : "f"(x)); return y;
}
__device__ __forceinline__ float siga(float x) { return fmaf(0.5f, tanha(0.5f * x), 0.5f); }
__device__ __forceinline__ int gcol6(int n, int j0) {
    return (n < 6) ? n : 6 + ((n - 6) / 6) * HH + j0 + ((n - 6) % 6);
}
__device__ __forceinline__ unsigned packbf(float lo, float hi) {
    __nv_bfloat162 p = __floats2bfloat162_rn(lo, hi);
    return *(unsigned*)&p;
}
__device__ __forceinline__ void mma16(float* d, const unsigned* a, const unsigned* b) {
    asm volatile("mma.sync.aligned.m16n8k16.row.col.f32.bf16.bf16.f32 "
                 "{%0,%1,%2,%3}, {%4,%5,%6,%7}, {%8,%9}, {%0,%1,%2,%3};"
                 : "+f"(d[0]), "+f"(d[1]), "+f"(d[2]), "+f"(d[3])
                 : "r"(a[0]), "r"(a[1]), "r"(a[2]), "r"(a[3]), "r"(b[0]), "r"(b[1]));
}
__device__ __forceinline__ void cp16(void* s, const void* g) {
    unsigned sa = (unsigned)__cvta_generic_to_shared(s);
    asm volatile("cp.async.cg.shared.global [%0], [%1], 16;" :: "r"(sa), "l"(g));
}
__device__ __forceinline__ uint4 ldcg4(const uint4* p) {
    uint4 v;
    asm volatile("ld.global.cg.v4.u32 {%0,%1,%2,%3}, [%4];"
                 : "=r"(v.x), "=r"(v.y), "=r"(v.z), "=r"(v.w) : "l"(p));
    return v;
}
__device__ __forceinline__ unsigned ldacq(const unsigned* p) {
    unsigned v;
    asm volatile("ld.global.acquire.gpu.u32 %0, [%1];" : "=r"(v) : "l"(p));
    return v;
}

// ---------- setup ----------
__global__ void bias_kernel(const float* __restrict__ Wk, const float* __restrict__ bk,
                            const float* __restrict__ Wr, const float* __restrict__ br) {
    int j = blockIdx.x * blockDim.x + threadIdx.x;
    if (j < GG) g_bias[j] = bk[j] + br[j] + Wk[FF * GG + j] + Wr[HH * GG + j];
}
__global__ void init_state_kernel() {
    int i = blockIdx.x * blockDim.x + threadIdx.x;
    if (i < 4 * AFQ * 4) ((unsigned*)g_haf)[i] = 0u;
    if (i < 8 * 32) g_grp[i] = 0u;
    if (i == 0) g_arrive = 0u;
}
__global__ void wct_kernel(const float* __restrict__ Wc) {
    int idx = blockIdx.x * blockDim.x + threadIdx.x;
    if (idx >= KKW * HH * HH) return;
    int kkidx = idx / HH, o = idx - kkidx * HH;
    int k = kkidx / HH, i = kkidx - k * HH;
    g_wct[idx] = Wc[(o * HH + i) * KKW + k];
}
__global__ void xp_kernel(const float* __restrict__ x) {
    __shared__ float tile[32][33];
    int t = blockIdx.z, f0 = blockIdx.x * 32, b0 = blockIdx.y * 32;
    int tx = threadIdx.x, ty = threadIdx.y;
    #pragma unroll
    for (int i = 0; i < 4; i++)
        tile[ty + 8 * i][tx] = x[((size_t)t * BB + b0 + ty + 8 * i) * FF + f0 + tx];
    __syncthreads();
    #pragma unroll
    for (int i = 0; i < 2; i++) {
        int k2l = ty + 8 * i;
        unsigned v = packbf(tile[tx][2 * k2l], tile[tx][2 * k2l + 1]);
        g_xp[((size_t)t * (FF/2) + f0/2 + k2l) * BB + b0 + tx] = v;
    }
}
__global__ void wkp_kernel(const float* __restrict__ Wk) {
    int idx = blockIdx.x * blockDim.x + threadIdx.x;
    if (idx >= (FF/2) * GP) return;
    int k2 = idx / GP, g = idx - k2 * GP;
    unsigned v = 0u;
    if (g < GG) v = packbf(Wk[(size_t)(2*k2) * GG + g], Wk[(size_t)(2*k2+1) * GG + g]);
    g_wkp[g * (FF/2) + k2] = v;
}

// ---------- precompute GEMM ----------
extern __shared__ unsigned psm[];
__global__ __launch_bounds__(256, 2) void xk_mma() {
    unsigned* A_s = psm;
    unsigned* B_s = psm + 128 * PAST;
    const int t = blockIdx.z, gt = blockIdx.y, bt = blockIdx.x;
    const int tid = threadIdx.x, w = tid >> 5, lane = tid & 31;
    const int gq = lane >> 2, tg = lane & 3;
    const int m0w = (w >> 2) * 64, n0w = (w & 3) * 32;

    for (int e = tid; e < 128 * 16; e += 256) {
        int r = e >> 4, seg = e & 15;
        cp16(A_s + r * PAST + seg * 4, g_wkp + (size_t)(gt * 128 + r) * 64 + seg * 4);
    }
    for (int e = tid; e < 64 * 32; e += 256) {
        int r = e >> 5, seg = e & 31;
        cp16(B_s + r * PBST + seg * 4,
             g_xp + ((size_t)t * 64 + r) * BB + bt * 128 + seg * 4);
    }
    asm volatile("cp.async.commit_group;");
    asm volatile("cp.async.wait_group 0;");
    __syncthreads();

    float acc[4][4][4];
    #pragma unroll
    for (int a = 0; a < 4; a++)
        #pragma unroll
        for (int b = 0; b < 4; b++)
            #pragma unroll
            for (int q = 0; q < 4; q++) acc[a][b][q] = 0.0f;

    #pragma unroll
    for (int k16 = 0; k16 < 8; k16++) {
        const int kb2 = k16 * 8;
        unsigned af[4][4];
        #pragma unroll
        for (int mt = 0; mt < 4; mt++) {
            const unsigned* ap = A_s + (m0w + mt * 16 + gq) * PAST + kb2 + tg;
            af[mt][0] = ap[0]; af[mt][1] = ap[8 * PAST];
            af[mt][2] = ap[4]; af[mt][3] = ap[8 * PAST + 4];
        }
        #pragma unroll
        for (int nt = 0; nt < 4; nt++) {
            const unsigned* bp = B_s + (kb2 + tg) * PBST + n0w + nt * 8 + gq;
            unsigned bf[2] = { bp[0], bp[4 * PBST] };
            #pragma unroll
            for (int mt = 0; mt < 4; mt++) mma16(acc[mt][nt], af[mt], bf);
        }
    }
    #pragma unroll
    for (int mt = 0; mt < 4; mt++) {
        #pragma unroll
        for (int rr = 0; rr < 2; rr++) {
            int g = gt * 128 + m0w + mt * 16 + gq + rr * 8;
            if (g >= GG) continue;
            float bv = g_bias[g];
            unsigned* out = g_xkb + (((size_t)t * GG + g) * BB + bt * 128 + n0w) / 2;
            #pragma unroll
            for (int nt = 0; nt < 4; nt++)
                out[nt * 4 + tg] = packbf(acc[mt][nt][rr * 2] + bv, acc[mt][nt][rr * 2 + 1] + bv);
        }
    }
}

// ---------- persistent recurrence: flat fast-path + group-pipelined slow path ----------
extern __shared__ unsigned dsm[];
__global__ __launch_bounds__(256, 1) void stage_persistent(const float* __restrict__ Wr)
{
    uint4* BF4 = (uint4*)dsm;                        // [NKK*32*2]
    float* xo_s = (float*)(dsm + 6144);              // [128][XOS]
    const int tid = threadIdx.x, blk = blockIdx.x;
    const int half = blk & 1, slice = blk >> 1;
    const int b0 = half * 128, j0 = slice * JC;
    const int w = tid >> 5, lane = tid & 31, gq = lane >> 2, tg = lane & 3;
    const int m0 = w * 16;
    const int row = m0 + (lane >> 1);
    const int jh  = lane & 1;
    unsigned* mygrp = &g_grp[(half * 4 + (slice >> 4)) * 32];

    // ---- build packed B fragments in smem (once) ----
    for (int e = tid; e < 6144; e += 256) {
        int kk = e >> 8, lane2 = (e >> 3) & 31, j = e & 7;
        int gq2 = lane2 >> 2, tg2 = lane2 & 3;
        int k2 = kk * 8 + tg2 + 4 * (j & 1);
        int n = (j >> 1) * 8 + gq2;
        unsigned v = 0u;
        if (n < NCOL) {
            int c = gcol6(n, j0);
            v = packbf(Wr[(size_t)(2*k2) * GG + c], Wr[(size_t)(2*k2+1) * GG + c]);
        }
        dsm[e] = v;
    }
    __syncthreads();

    float c_reg[3] = {0.0f, 0.0f, 0.0f};

    float xk6[6], xkg[12];
    auto pre_xk = [&](int t) {
        const __nv_bfloat16* base =
            (const __nv_bfloat16*)g_xkb + (size_t)t * GG * BB + b0 + row;
        #pragma unroll
        for (int c = 0; c < 6; c++) xk6[c] = __bfloat162float(base[(size_t)c * BB]);
        #pragma unroll
        for (int q2 = 0; q2 < 3; q2++) {
            int jj = 3 * jh + q2;
            #pragma unroll
            for (int gc = 0; gc < 4; gc++)
                xkg[q2 * 4 + gc] =
                    __bfloat162float(base[(size_t)(6 + gc * HH + j0 + jj) * BB]);
        }
    };
    pre_xk(0);

    for (int t = 0; t < TT; t++) {
        const uint4* AF  = g_haf + (size_t)((t & 1) * 2 + half) * AFQ;
        unsigned*    AFn = (unsigned*)(g_haf + (size_t)(((t + 1) & 1) * 2 + half) * AFQ);

        float acc[NT][4];
        #pragma unroll
        for (int nt = 0; nt < NT; nt++)
            #pragma unroll
            for (int q = 0; q < 4; q++) acc[nt][q] = 0.0f;

        const uint4* afp = AF + w * 32 + lane;
        const uint4* bfp = BF4 + lane * 2;

        auto chunk = [&](int kk) {
            uint4 a = ldcg4(afp + kk * 256);
            uint4 p = bfp[kk * 64];
            uint4 q = bfp[kk * 64 + 1];
            unsigned af[4] = { a.x, a.y, a.z, a.w };
            unsigned bf0[2] = { p.x, p.y }, bf1[2] = { p.z, p.w };
            unsigned bf2[2] = { q.x, q.y }, bf3[2] = { q.z, q.w };
            mma16(acc[0], af, bf0);
            mma16(acc[1], af, bf1);
            mma16(acc[2], af, bf2);
            mma16(acc[3], af, bf3);
        };

        // ---- fast path: root already released? ----
        unsigned ready = 1u;
        if (lane == 0) ready = (ldacq(&g_arrive) >= (unsigned)t * NBLK) ? 1u : 0u;
        ready = __shfl_sync(0xFFFFFFFFu, ready, 0);

        if (ready) {
            #pragma unroll
            for (int kk = 0; kk < NKK; kk++) chunk(kk);
        } else {
            // ---- slow path: consume group-by-group as producers arrive ----
            #pragma unroll
            for (int g = 0; g < 4; g++) {
                if (lane == 0) {
                    const unsigned* gp = &g_grp[(half * 4 + g) * 32];
                    unsigned tgt = (unsigned)t * 16u, v;
                    do { v = ldacq(gp); } while (v < tgt);
                }
                __syncwarp();
                #pragma unroll
                for (int j = 0; j < 6; j++) chunk(6 * g + j);
            }
        }

        // ---- xo to warp-private smem slice ----
        {
            int r = m0 + gq;
            #pragma unroll
            for (int nt = 0; nt < NT; nt++) {
                int cb = nt * 8 + 2 * tg;
                xo_s[r * XOS + cb]           = acc[nt][0];
                xo_s[r * XOS + cb + 1]       = acc[nt][1];
                xo_s[(r + 8) * XOS + cb]     = acc[nt][2];
                xo_s[(r + 8) * XOS + cb + 1] = acc[nt][3];
            }
        }
        __syncwarp();

        // ---- gates: warp-local, 2 lanes/row, 3 jj each ----
        {
            const float* xr = xo_s + row * XOS;
            float a0 = xr[0] + xk6[0], a1 = xr[1] + xk6[1], a2 = xr[2] + xk6[2];
            float m = fmaxf(a0, fmaxf(a1, a2));
            float e0 = __expf(a0 - m), e1 = __expf(a1 - m), e2 = __expf(a2 - m);
            float rs = __fdividef(1.0f, e0 + e1 + e2);
            float f0 = e0 * rs, f1 = (e0 + e1) * rs;
            float b0v = xr[3] + xk6[3], b1v = xr[4] + xk6[4], b2v = xr[5] + xk6[5];
            m = fmaxf(b0v, fmaxf(b1v, b2v));
            e0 = __expf(b0v - m); e1 = __expf(b1v - m); e2 = __expf(b2v - m);
            rs = __fdividef(1.0f, e0 + e1 + e2);
            float i1 = (e1 + e2) * rs, i2 = e2 * rs;
            float cd = 1.0f - (f0 + f1 + 1.0f) * (1.0f / 3.0f);
            const bool hist = (t >= TT - KKW);
            const int slot = t % KKW;
            float hv[3];
            #pragma unroll
            for (int q2 = 0; q2 < 3; q2++) {
                int jj = 3 * jh + q2;
                int lg = (j0 + jj) >> 7;
                float fm = (lg == 0) ? f0 : ((lg == 1) ? f1 : 1.0f);
                float im = (lg == 0) ? 1.0f : ((lg == 1) ? i1 : i2);
                float ov = fm * im;
                float fg = siga(xr[6 + jj]      + xkg[q2 * 4 + 0]);
                float ig = siga(xr[12 + jj]     + xkg[q2 * 4 + 1]);
                float og = siga(xr[18 + jj]     + xkg[q2 * 4 + 2]);
                float ci = tanha(xr[24 + jj]    + xkg[q2 * 4 + 3]);
                float cn = c_reg[q2] * (ov * fg + fm - ov) + ci * (ov * ig + im - ov);
                c_reg[q2] = cn;
                hv[q2] = og * tanha(cn);
            }
            float h3 = __shfl_xor_sync(0xFFFFFFFFu, hv[0], 1);
            const int r = row;
            auto put = [&](int c, unsigned v) {
                int kk = c >> 3, o = c & 7;
                int lane3 = ((r & 7) << 2) | (o & 3);
                int comp = ((o >> 2) << 1) | ((r >> 3) & 1);
                AFn[(((kk << 3) + (r >> 4)) * 32 + lane3) * 4 + comp] = v;
            };
            if (jh == 0) {
                put(3 * slice,     packbf(hv[0], hv[1]));
                put(3 * slice + 1, packbf(hv[2], h3));
            } else {
                put(3 * slice + 2, packbf(hv[1], hv[2]));
            }
            if (hist) {
                #pragma unroll
                for (int q2 = 0; q2 < 3; q2++)
                    g_hist_h[slot * BB * HH + (b0 + r) * HH + j0 + 3 * jh + q2] = hv[q2];
                if (jh == 0 && slice == 0)
                    g_hist_d[slot * BB + b0 + r] = cd;
            }
        }

        // ---- single block barrier, then flat root + group arrive ----
        __syncthreads();
        if (tid == 0) {
            __threadfence();
            atomicAdd(&g_arrive, 1u);
            atomicAdd(mygrp, 1u);
        }
        if (t + 1 < TT) pre_xk(t + 1);
    }
}

// ---------- final head ----------
__global__ void dis_kernel() {
    int b = threadIdx.x;
    if (b >= BB) return;
    float cum = 0.0f, v[KKW];
    #pragma unroll
    for (int k = 0; k < KKW; k++) {
        cum += g_hist_d[((TT - KKW + k) % KKW) * BB + b];
        v[k] = cum;
    }
    float m = v[0];
    #pragma unroll
    for (int k = 1; k < KKW; k++) m = fmaxf(m, v[k]);
    float s = 0.0f;
    #pragma unroll
    for (int k = 0; k < KKW; k++) { v[k] = expf(v[k] - m); s += v[k]; }
    float inv = 1.0f / s;
    #pragma unroll
    for (int k = 0; k < KKW; k++) g_dis[b * KKW + k] = v[k] * inv;
}
__global__ void wh_kernel() {
    int idx = blockIdx.x * blockDim.x + threadIdx.x;
    if (idx >= BB * HH) return;
    int b = idx / HH;
    float acc = 0.0f;
    #pragma unroll
    for (int k = 0; k < KKW; k++) {
        float v = g_hist_h[((TT - KKW + k) % KKW) * BB * HH + idx] * g_dis[b * KKW + k];
        g_wh[k * BB * HH + idx] = v;
        acc += v;
    }
    g_M[idx] = acc * (1.0f / KKW);
}
__global__ __launch_bounds__(256) void conv_kernel(const float* __restrict__ bc) {
    __shared__ float Asm[16][65];
    __shared__ float Bsm[16][64];
    const int tx = threadIdx.x & 15, ty = threadIdx.x >> 4;
    const int b0 = blockIdx.y * 64, o0 = blockIdx.x * 64;
    float acc[4][4] = {};
    for (int kk0 = 0; kk0 < KKW * HH; kk0 += 16) {
        #pragma unroll
        for (int x2 = threadIdx.x; x2 < 1024; x2 += 256) {
            int bb = x2 >> 4, kk = x2 & 15;
            int kkidx = kk0 + kk, k = kkidx / HH, i = kkidx - k * HH;
            Asm[kk][bb] = g_wh[k * BB * HH + (b0 + bb) * HH + i];
        }
        #pragma unroll
        for (int x2 = threadIdx.x; x2 < 1024; x2 += 256) {
            int kk = x2 >> 6, oo = x2 & 63;
            Bsm[kk][oo] = g_wct[(size_t)(kk0 + kk) * HH + o0 + oo];
        }
        __syncthreads();
        #pragma unroll
        for (int kk = 0; kk < 16; kk++) {
            float av[4], bv[4];
            #pragma unroll
            for (int m = 0; m < 4; m++) av[m] = Asm[kk][ty * 4 + m];
            #pragma unroll
            for (int n = 0; n < 4; n++) bv[n] = Bsm[kk][tx * 4 + n];
            #pragma unroll
            for (int m = 0; m < 4; m++)
                #pragma unroll
                for (int n = 0; n < 4; n++) acc[m][n] += av[m] * bv[n];
        }
        __syncthreads();
    }
    #pragma unroll
    for (int m = 0; m < 4; m++)
        #pragma unroll
        for (int n = 0; n < 4; n++)
            g_conv[(b0 + ty * 4 + m) * HH + o0 + tx * 4 + n] = acc[m][n] + bc[o0 + tx * 4 + n];
}
__global__ void p_kernel(const float* __restrict__ Ws, const float* __restrict__ bs) {
    int b = blockIdx.x, s2 = threadIdx.x;
    float acc = bs[s2];
    for (int i = 0; i < HH; i++) acc += g_M[b * HH + i] * Ws[i * SS + s2];
    g_P[b * SS + s2] = fmaxf(acc, 0.0f);
}
__global__ void theme_kernel(const float* __restrict__ Wrs, const float* __restrict__ brs) {
    int b = blockIdx.x, o = threadIdx.x;
    float acc = brs[o];
    #pragma unroll 8
    for (int s2 = 0; s2 < SS; s2++) acc += g_P[b * SS + s2] * Wrs[s2 * HH + o];
    g_theme[b * HH + o] = sigmoidf(acc);
}
__global__ void out_kernel(const float* __restrict__ Wo, const float* __restrict__ bo,
                           float* __restrict__ out) {
    int b = blockIdx.x;
    __shared__ float red[128];
    const float* hfin = g_hist_h + ((TT - 1) % KKW) * BB * HH;
    float acc = 0.0f;
    for (int i = threadIdx.x; i < HH; i += 128) {
        float rnn = g_theme[b * HH + i] * g_conv[b * HH + i] + hfin[b * HH + i];
        acc += rnn * Wo[i];
    }
    red[threadIdx.x] = acc;
    __syncthreads();
    for (int s = 64; s > 0; s >>= 1) {
        if (threadIdx.x < s) red[threadIdx.x] += red[threadIdx.x + s];
        __syncthreads();
    }
    if (threadIdx.x == 0) out[b] = sigmoidf(red[0] + bo[0]);
}

// ---------- host ----------
extern "C" void kernel_launch(void* const* d_in, const int* in_sizes, int n_in,
                              void* d_out, int out_size)
{
    (void)in_sizes; (void)n_in; (void)out_size;
    const float* x   = (const float*)d_in[0];
    const float* Wk  = (const float*)d_in[1];
    const float* bk  = (const float*)d_in[2];
    const float* Wr  = (const float*)d_in[3];
    const float* br  = (const float*)d_in[4];
    const float* Ws  = (const float*)d_in[5];
    const float* bs  = (const float*)d_in[6];
    const float* Wrs = (const float*)d_in[7];
    const float* brs = (const float*)d_in[8];
    const float* Wc  = (const float*)d_in[9];
    const float* bc  = (const float*)d_in[10];
    const float* Wo  = (const float*)d_in[11];
    const float* bo  = (const float*)d_in[12];

    cudaFuncSetAttribute(stage_persistent, cudaFuncAttributeMaxDynamicSharedMemorySize, SMEM_BYTES);
    cudaFuncSetAttribute(xk_mma, cudaFuncAttributeMaxDynamicSharedMemorySize, PSMEM);

    bias_kernel<<<(GG + 255) / 256, 256>>>(Wk, bk, Wr, br);
    init_state_kernel<<<(4 * AFQ * 4 + 255) / 256, 256>>>();
    wct_kernel<<<(KKW * HH * HH + 255) / 256, 256>>>(Wc);
    xp_kernel<<<dim3(FF / 32, BB / 32, TT), dim3(32, 8)>>>(x);
    wkp_kernel<<<((FF/2) * GP + 255) / 256, 256>>>(Wk);
    xk_mma<<<dim3(2, 13, TT), 256, PSMEM>>>();

    stage_persistent<<<NBLK, 256, SMEM_BYTES>>>(Wr);

    dis_kernel<<<1, 256>>>();
    wh_kernel<<<(BB * HH + 255) / 256, 256>>>();
    conv_kernel<<<dim3(HH / 64, BB / 64), 256>>>(bc);
    p_kernel<<<BB, SS>>>(Ws, bs);
    theme_kernel<<<BB, HH>>>(Wrs, brs);
    out_kernel<<<BB, 128>>>(Wo, bo, (float*)d_out);
}

// round 15
// speedup vs baseline: 1.2635x; 1.2635x over previous
#include <cuda_runtime.h>
#include <cuda_bf16.h>
#include <math.h>
#include <stdint.h>

#define TT 256
#define BB 256
#define FF 128
#define LL 3
#define HH 384
#define KKW 10
#define GG 1542
#define SS 64

#define NBLK 128        // 2 batch-halves x 64 col-slices
#define JC 6
#define NCOL 30
#define NT 4
#define XOS 33
#define NKK 24          // h k16 chunks (384/16)
#define NKX 8           // x k16 chunks (128/16)
#define AFQ 6144        // uint4 per (parity,half): 24*8*32
#define XFQ 2048        // uint4 per (t,half): 8*8*32
#define SMEM_BYTES ((6144 + 2048 + 128*XOS)*4)

static __device__ uint4    g_haf[4 * AFQ];                  // [parity][half] h fragments
static __device__ uint4    g_xaf[(size_t)TT * 2 * XFQ];     // [t][half] x fragments (16MB)
static __device__ float g_hist_h[KKW * BB * HH];
static __device__ float g_hist_d[KKW * BB];
static __device__ float g_dis[BB * KKW];
static __device__ float g_wh[KKW * BB * HH];
static __device__ float g_M[BB * HH];
static __device__ float g_P[BB * SS];
static __device__ float g_theme[BB * HH];
static __device__ float g_conv[BB * HH];
static __device__ float g_bias[GG];
static __device__ float g_wct[KKW * HH * HH];
static __device__ unsigned g_arrive;

__device__ __forceinline__ float sigmoidf(float x) { return 1.0f / (1.0f + expf(-x)); }
__device__ __forceinline__ float tanha(float x) {
    float y; asm("tanh.approx.f32 %0, %1;" : "=f"(y) : "f"(x)); return y;
}
__device__ __forceinline__ float siga(float x) { return fmaf(0.5f, tanha(0.5f * x), 0.5f); }
__device__ __forceinline__ int gcol6(int n, int j0) {
    return (n < 6) ? n : 6 + ((n - 6) / 6) * HH + j0 + ((n - 6) % 6);
}
__device__ __forceinline__ unsigned packbf(float lo, float hi) {
    __nv_bfloat162 p = __floats2bfloat162_rn(lo, hi);
    return *(unsigned*)&p;
}
__device__ __forceinline__ void mma16(float* d, const unsigned* a, const unsigned* b) {
    asm volatile("mma.sync.aligned.m16n8k16.row.col.f32.bf16.bf16.f32 "
                 "{%0,%1,%2,%3}, {%4,%5,%6,%7}, {%8,%9}, {%0,%1,%2,%3};"
                 : "+f"(d[0]), "+f"(d[1]), "+f"(d[2]), "+f"(d[3])
                 : "r"(a[0]), "r"(a[1]), "r"(a[2]), "r"(a[3]), "r"(b[0]), "r"(b[1]));
}
__device__ __forceinline__ uint4 ldcg4(const uint4* p) {
    uint4 v;
    asm volatile("ld.global.cg.v4.u32 {%0,%1,%2,%3}, [%4];"
                 : "=r"(v.x), "=r"(v.y), "=r"(v.z), "=r"(v.w) : "l"(p));
    return v;
}
__device__ __forceinline__ unsigned ldacq(const unsigned* p) {
    unsigned v;
    asm volatile("ld.global.acquire.gpu.u32 %0, [%1];" : "=r"(v) : "l"(p));
    return v;
}

// ---------- setup ----------
__global__ void bias_kernel(const float* __restrict__ Wk, const float* __restrict__ bk,
                            const float* __restrict__ Wr, const float* __restrict__ br) {
    int j = blockIdx.x * blockDim.x + threadIdx.x;
    if (j < GG) g_bias[j] = bk[j] + br[j] + Wk[FF * GG + j] + Wr[HH * GG + j];
}
__global__ void init_state_kernel() {
    int i = blockIdx.x * blockDim.x + threadIdx.x;
    if (i < 4 * AFQ * 4) ((unsigned*)g_haf)[i] = 0u;
    if (i == 0) g_arrive = 0u;
}
__global__ void wct_kernel(const float* __restrict__ Wc) {
    int idx = blockIdx.x * blockDim.x + threadIdx.x;
    if (idx >= KKW * HH * HH) return;
    int kkidx = idx / HH, o = idx - kkidx * HH;
    int k = kkidx / HH, i = kkidx - k * HH;
    g_wct[idx] = Wc[(o * HH + i) * KKW + k];
}
// x -> fragment layout [t][half]: element pair (r, k2) of x[t][b0+r][2k2..2k2+1]
__global__ void xfrag_kernel(const float* __restrict__ x) {
    int half = blockIdx.x, t = blockIdx.y;
    unsigned* out = (unsigned*)(g_xaf + ((size_t)t * 2 + half) * XFQ);
    const float* xb = x + ((size_t)t * BB + half * 128) * FF;
    for (int e = threadIdx.x; e < 128 * 64; e += 256) {
        int r = e >> 6, k2 = e & 63;
        unsigned v = packbf(xb[r * FF + 2 * k2], xb[r * FF + 2 * k2 + 1]);
        int kk = k2 >> 3, tg = k2 & 3, k4 = (k2 >> 2) & 1;
        int u4 = kk * 256 + (r >> 4) * 32 + ((r & 7) << 2) + tg;
        int comp = (k4 << 1) | ((r >> 3) & 1);
        out[u4 * 4 + comp] = v;
    }
}

// ---------- persistent recurrence: R11 structure + fused x@Wk (pre-barrier) ----------
extern __shared__ unsigned dsm[];
__global__ __launch_bounds__(256, 1) void stage_persistent(
    const float* __restrict__ Wr, const float* __restrict__ Wk)
{
    uint4* BF4 = (uint4*)dsm;                        // Wr frags [24*32*8 u32]
    unsigned* wkf = dsm + 6144;                      // Wk frags [8*32*8 u32]
    float* xo_s = (float*)(dsm + 6144 + 2048);       // [128][XOS]
    const int tid = threadIdx.x, blk = blockIdx.x;
    const int half = blk & 1, slice = blk >> 1;
    const int b0 = half * 128, j0 = slice * JC;
    const int w = tid >> 5, lane = tid & 31, gq = lane >> 2, tg = lane & 3;
    const int m0 = w * 16;
    const int row = m0 + (lane >> 1);
    const int jh  = lane & 1;

    // ---- build packed Wr fragments (once) ----
    for (int e = tid; e < 6144; e += 256) {
        int kk = e >> 8, lane2 = (e >> 3) & 31, j = e & 7;
        int gq2 = lane2 >> 2, tg2 = lane2 & 3;
        int k2 = kk * 8 + tg2 + 4 * (j & 1);
        int n = (j >> 1) * 8 + gq2;
        unsigned v = 0u;
        if (n < NCOL) {
            int c = gcol6(n, j0);
            v = packbf(Wr[(size_t)(2*k2) * GG + c], Wr[(size_t)(2*k2+1) * GG + c]);
        }
        dsm[e] = v;
    }
    // ---- build packed Wk fragments (once, K=128 -> 8 chunks) ----
    for (int e = tid; e < 2048; e += 256) {
        int kk = e >> 8, lane2 = (e >> 3) & 31, j = e & 7;
        int gq2 = lane2 >> 2, tg2 = lane2 & 3;
        int k2 = kk * 8 + tg2 + 4 * (j & 1);
        int n = (j >> 1) * 8 + gq2;
        unsigned v = 0u;
        if (n < NCOL) {
            int c = gcol6(n, j0);
            v = packbf(Wk[(size_t)(2*k2) * GG + c], Wk[(size_t)(2*k2+1) * GG + c]);
        }
        wkf[e] = v;
    }
    __syncthreads();

    float c_reg[3] = {0.0f, 0.0f, 0.0f};

    // bias columns (constant over t) into registers
    float xk6[6], xkg[12];
    {
        #pragma unroll
        for (int c = 0; c < 6; c++) xk6[c] = g_bias[c];
        #pragma unroll
        for (int q2 = 0; q2 < 3; q2++) {
            int jj = 3 * jh + q2;
            #pragma unroll
            for (int gc = 0; gc < 4; gc++)
                xkg[q2 * 4 + gc] = g_bias[6 + gc * HH + j0 + jj];
        }
    }

    for (int t = 0; t < TT; t++) {
        const uint4* AF  = g_haf + (size_t)((t & 1) * 2 + half) * AFQ;
        unsigned*    AFn = (unsigned*)(g_haf + (size_t)(((t + 1) & 1) * 2 + half) * AFQ);
        const uint4* AX  = g_xaf + ((size_t)t * 2 + half) * XFQ;

        float acc[NT][4];
        #pragma unroll
        for (int nt = 0; nt < NT; nt++)
            #pragma unroll
            for (int q = 0; q < 4; q++) acc[nt][q] = 0.0f;

        const uint4* afp = AF + w * 32 + lane;
        const uint4* axp = AX + w * 32 + lane;
        const uint4* bfp = BF4 + lane * 2;
        const uint4* bxp = (const uint4*)wkf + lane * 2;

        // ---- x@Wk part FIRST (independent of h(t); overlaps barrier slack) ----
        #pragma unroll
        for (int kk = 0; kk < NKX; kk++) {
            uint4 a = ldcg4(axp + kk * 256);
            uint4 p = bxp[kk * 64];
            uint4 q = bxp[kk * 64 + 1];
            unsigned af[4] = { a.x, a.y, a.z, a.w };
            unsigned bf0[2] = { p.x, p.y }, bf1[2] = { p.z, p.w };
            unsigned bf2[2] = { q.x, q.y }, bf3[2] = { q.z, q.w };
            mma16(acc[0], af, bf0);
            mma16(acc[1], af, bf1);
            mma16(acc[2], af, bf2);
            mma16(acc[3], af, bf3);
        }

        // ---- per-warp wait for all h(t) fragments ----
        {
            unsigned tgt = (unsigned)t * NBLK;
            if (lane == 0) {
                unsigned v;
                do { v = ldacq(&g_arrive); } while (v < tgt);
            }
            __syncwarp();
        }

        // ---- h@Wr part ----
        #pragma unroll
        for (int kk = 0; kk < NKK; kk++) {
            uint4 a = ldcg4(afp + kk * 256);
            uint4 p = bfp[kk * 64];
            uint4 q = bfp[kk * 64 + 1];
            unsigned af[4] = { a.x, a.y, a.z, a.w };
            unsigned bf0[2] = { p.x, p.y }, bf1[2] = { p.z, p.w };
            unsigned bf2[2] = { q.x, q.y }, bf3[2] = { q.z, q.w };
            mma16(acc[0], af, bf0);
            mma16(acc[1], af, bf1);
            mma16(acc[2], af, bf2);
            mma16(acc[3], af, bf3);
        }

        // ---- xo to warp-private smem slice ----
        {
            int r = m0 + gq;
            #pragma unroll
            for (int nt = 0; nt < NT; nt++) {
                int cb = nt * 8 + 2 * tg;
                xo_s[r * XOS + cb]           = acc[nt][0];
                xo_s[r * XOS + cb + 1]       = acc[nt][1];
                xo_s[(r + 8) * XOS + cb]     = acc[nt][2];
                xo_s[(r + 8) * XOS + cb + 1] = acc[nt][3];
            }
        }
        __syncwarp();

        // ---- gates: warp-local, 2 lanes/row, 3 jj each ----
        {
            const float* xr = xo_s + row * XOS;
            float a0 = xr[0] + xk6[0], a1 = xr[1] + xk6[1], a2 = xr[2] + xk6[2];
            float m = fmaxf(a0, fmaxf(a1, a2));
            float e0 = __expf(a0 - m), e1 = __expf(a1 - m), e2 = __expf(a2 - m);
            float rs = __fdividef(1.0f, e0 + e1 + e2);
            float f0 = e0 * rs, f1 = (e0 + e1) * rs;
            float b0v = xr[3] + xk6[3], b1v = xr[4] + xk6[4], b2v = xr[5] + xk6[5];
            m = fmaxf(b0v, fmaxf(b1v, b2v));
            e0 = __expf(b0v - m); e1 = __expf(b1v - m); e2 = __expf(b2v - m);
            rs = __fdividef(1.0f, e0 + e1 + e2);
            float i1 = (e1 + e2) * rs, i2 = e2 * rs;
            float cd = 1.0f - (f0 + f1 + 1.0f) * (1.0f / 3.0f);
            const bool hist = (t >= TT - KKW);
            const int slot = t % KKW;
            float hv[3];
            #pragma unroll
            for (int q2 = 0; q2 < 3; q2++) {
                int jj = 3 * jh + q2;
                int lg = (j0 + jj) >> 7;
                float fm = (lg == 0) ? f0 : ((lg == 1) ? f1 : 1.0f);
                float im = (lg == 0) ? 1.0f : ((lg == 1) ? i1 : i2);
                float ov = fm * im;
                float fg = siga(xr[6 + jj]      + xkg[q2 * 4 + 0]);
                float ig = siga(xr[12 + jj]     + xkg[q2 * 4 + 1]);
                float og = siga(xr[18 + jj]     + xkg[q2 * 4 + 2]);
                float ci = tanha(xr[24 + jj]    + xkg[q2 * 4 + 3]);
                float cn = c_reg[q2] * (ov * fg + fm - ov) + ci * (ov * ig + im - ov);
                c_reg[q2] = cn;
                hv[q2] = og * tanha(cn);
            }
            float h3 = __shfl_xor_sync(0xFFFFFFFFu, hv[0], 1);
            const int r = row;
            auto put = [&](int c, unsigned v) {
                int kk = c >> 3, o = c & 7;
                int lane3 = ((r & 7) << 2) | (o & 3);
                int comp = ((o >> 2) << 1) | ((r >> 3) & 1);
                AFn[(((kk << 3) + (r >> 4)) * 32 + lane3) * 4 + comp] = v;
            };
            if (jh == 0) {
                put(3 * slice,     packbf(hv[0], hv[1]));
                put(3 * slice + 1, packbf(hv[2], h3));
            } else {
                put(3 * slice + 2, packbf(hv[1], hv[2]));
            }
            if (hist) {
                #pragma unroll
                for (int q2 = 0; q2 < 3; q2++)
                    g_hist_h[slot * BB * HH + (b0 + r) * HH + j0 + 3 * jh + q2] = hv[q2];
                if (jh == 0 && slice == 0)
                    g_hist_d[slot * BB + b0 + r] = cd;
            }
        }

        // ---- single block barrier, then flat arrive ----
        __syncthreads();
        if (tid == 0) {
            __threadfence();
            atomicAdd(&g_arrive, 1u);
        }
    }
}

// ---------- final head ----------
__global__ void dis_kernel() {
    int b = threadIdx.x;
    if (b >= BB) return;
    float cum = 0.0f, v[KKW];
    #pragma unroll
    for (int k = 0; k < KKW; k++) {
        cum += g_hist_d[((TT - KKW + k) % KKW) * BB + b];
        v[k] = cum;
    }
    float m = v[0];
    #pragma unroll
    for (int k = 1; k < KKW; k++) m = fmaxf(m, v[k]);
    float s = 0.0f;
    #pragma unroll
    for (int k = 0; k < KKW; k++) { v[k] = expf(v[k] - m); s += v[k]; }
    float inv = 1.0f / s;
    #pragma unroll
    for (int k = 0; k < KKW; k++) g_dis[b * KKW + k] = v[k] * inv;
}
__global__ void wh_kernel() {
    int idx = blockIdx.x * blockDim.x + threadIdx.x;
    if (idx >= BB * HH) return;
    int b = idx / HH;
    float acc = 0.0f;
    #pragma unroll
    for (int k = 0; k < KKW; k++) {
        float v = g_hist_h[((TT - KKW + k) % KKW) * BB * HH + idx] * g_dis[b * KKW + k];
        g_wh[k * BB * HH + idx] = v;
        acc += v;
    }
    g_M[idx] = acc * (1.0f / KKW);
}
__global__ __launch_bounds__(256) void conv_kernel(const float* __restrict__ bc) {
    __shared__ float Asm[16][65];
    __shared__ float Bsm[16][64];
    const int tx = threadIdx.x & 15, ty = threadIdx.x >> 4;
    const int b0 = blockIdx.y * 64, o0 = blockIdx.x * 64;
    float acc[4][4] = {};
    for (int kk0 = 0; kk0 < KKW * HH; kk0 += 16) {
        #pragma unroll
        for (int x2 = threadIdx.x; x2 < 1024; x2 += 256) {
            int bb = x2 >> 4, kk = x2 & 15;
            int kkidx = kk0 + kk, k = kkidx / HH, i = kkidx - k * HH;
            Asm[kk][bb] = g_wh[k * BB * HH + (b0 + bb) * HH + i];
        }
        #pragma unroll
        for (int x2 = threadIdx.x; x2 < 1024; x2 += 256) {
            int kk = x2 >> 6, oo = x2 & 63;
            Bsm[kk][oo] = g_wct[(size_t)(kk0 + kk) * HH + o0 + oo];
        }
        __syncthreads();
        #pragma unroll
        for (int kk = 0; kk < 16; kk++) {
            float av[4], bv[4];
            #pragma unroll
            for (int m = 0; m < 4; m++) av[m] = Asm[kk][ty * 4 + m];
            #pragma unroll
            for (int n = 0; n < 4; n++) bv[n] = Bsm[kk][tx * 4 + n];
            #pragma unroll
            for (int m = 0; m < 4; m++)
                #pragma unroll
                for (int n = 0; n < 4; n++) acc[m][n] += av[m] * bv[n];
        }
        __syncthreads();
    }
    #pragma unroll
    for (int m = 0; m < 4; m++)
        #pragma unroll
        for (int n = 0; n < 4; n++)
            g_conv[(b0 + ty * 4 + m) * HH + o0 + tx * 4 + n] = acc[m][n] + bc[o0 + tx * 4 + n];
}
__global__ void p_kernel(const float* __restrict__ Ws, const float* __restrict__ bs) {
    int b = blockIdx.x, s2 = threadIdx.x;
    float acc = bs[s2];
    for (int i = 0; i < HH; i++) acc += g_M[b * HH + i] * Ws[i * SS + s2];
    g_P[b * SS + s2] = fmaxf(acc, 0.0f);
}
__global__ void theme_kernel(const float* __restrict__ Wrs, const float* __restrict__ brs) {
    int b = blockIdx.x, o = threadIdx.x;
    float acc = brs[o];
    #pragma unroll 8
    for (int s2 = 0; s2 < SS; s2++) acc += g_P[b * SS + s2] * Wrs[s2 * HH + o];
    g_theme[b * HH + o] = sigmoidf(acc);
}
__global__ void out_kernel(const float* __restrict__ Wo, const float* __restrict__ bo,
                           float* __restrict__ out) {
    int b = blockIdx.x;
    __shared__ float red[128];
    const float* hfin = g_hist_h + ((TT - 1) % KKW) * BB * HH;
    float acc = 0.0f;
    for (int i = threadIdx.x; i < HH; i += 128) {
        float rnn = g_theme[b * HH + i] * g_conv[b * HH + i] + hfin[b * HH + i];
        acc += rnn * Wo[i];
    }
    red[threadIdx.x] = acc;
    __syncthreads();
    for (int s = 64; s > 0; s >>= 1) {
        if (threadIdx.x < s) red[threadIdx.x] += red[threadIdx.x + s];
        __syncthreads();
    }
    if (threadIdx.x == 0) out[b] = sigmoidf(red[0] + bo[0]);
}

// ---------- host ----------
extern "C" void kernel_launch(void* const* d_in, const int* in_sizes, int n_in,
                              void* d_out, int out_size)
{
    (void)in_sizes; (void)n_in; (void)out_size;
    const float* x   = (const float*)d_in[0];
    const float* Wk  = (const float*)d_in[1];
    const float* bk  = (const float*)d_in[2];
    const float* Wr  = (const float*)d_in[3];
    const float* br  = (const float*)d_in[4];
    const float* Ws  = (const float*)d_in[5];
    const float* bs  = (const float*)d_in[6];
    const float* Wrs = (const float*)d_in[7];
    const float* brs = (const float*)d_in[8];
    const float* Wc  = (const float*)d_in[9];
    const float* bc  = (const float*)d_in[10];
    const float* Wo  = (const float*)d_in[11];
    const float* bo  = (const float*)d_in[12];

    cudaFuncSetAttribute(stage_persistent, cudaFuncAttributeMaxDynamicSharedMemorySize, SMEM_BYTES);

    bias_kernel<<<(GG + 255) / 256, 256>>>(Wk, bk, Wr, br);
    init_state_kernel<<<(4 * AFQ * 4 + 255) / 256, 256>>>();
    wct_kernel<<<(KKW * HH * HH + 255) / 256, 256>>>(Wc);
    xfrag_kernel<<<dim3(2, TT), 256>>>(x);

    stage_persistent<<<NBLK, 256, SMEM_BYTES>>>(Wr, Wk);

    dis_kernel<<<1, 256>>>();
    wh_kernel<<<(BB * HH + 255) / 256, 256>>>();
    conv_kernel<<<dim3(HH / 64, BB / 64), 256>>>(bc);
    p_kernel<<<BB, SS>>>(Ws, bs);
    theme_kernel<<<BB, HH>>>(Wrs, brs);
    out_kernel<<<BB, 128>>>(Wo, bo, (float*)d_out);
}

// round 16
// speedup vs baseline: 1.4349x; 1.1357x over previous
#include <cuda_runtime.h>
#include <cuda_bf16.h>
#include <math.h>
#include <stdint.h>

#define TT 256
#define BB 256
#define FF 128
#define LL 3
#define HH 384
#define KKW 10
#define GG 1542
#define SS 64

#define NBLK 128        // 2 batch-halves x 64 col-slices
#define JC 6
#define NCOL 30
#define NT 4
#define XOS 33
#define NKK 24          // h k16 chunks (384/16)
#define NKX 8           // x k16 chunks (128/16)
#define AFQ 6144        // uint4 per (parity,half): 24*8*32
#define XFQ 2048        // uint4 per (t,half): 8*8*32
#define SMEM_BYTES ((6144 + 2048 + 128*XOS)*4)

static __device__ uint4    g_haf[4 * AFQ];                  // [parity][half] h fragments
static __device__ uint4    g_xaf[(size_t)TT * 2 * XFQ];     // [t][half] x fragments (16MB)
static __device__ float g_hist_h[KKW * BB * HH];
static __device__ float g_hist_d[KKW * BB];
static __device__ float g_dis[BB * KKW];
static __device__ float g_wh[KKW * BB * HH];
static __device__ float g_M[BB * HH];
static __device__ float g_P[BB * SS];
static __device__ float g_theme[BB * HH];
static __device__ float g_conv[BB * HH];
static __device__ float g_bias[GG];
static __device__ float g_wct[KKW * HH * HH];
static __device__ unsigned g_arrive;

__device__ __forceinline__ float sigmoidf(float x) { return 1.0f / (1.0f + expf(-x)); }
__device__ __forceinline__ float tanha(float x) {
    float y; asm("tanh.approx.f32 %0, %1;" : "=f"(y) : "f"(x)); return y;
}
__device__ __forceinline__ float siga(float x) { return fmaf(0.5f, tanha(0.5f * x), 0.5f); }
__device__ __forceinline__ int gcol6(int n, int j0) {
    return (n < 6) ? n : 6 + ((n - 6) / 6) * HH + j0 + ((n - 6) % 6);
}
__device__ __forceinline__ unsigned packbf(float lo, float hi) {
    __nv_bfloat162 p = __floats2bfloat162_rn(lo, hi);
    return *(unsigned*)&p;
}
__device__ __forceinline__ void mma16(float* d, const unsigned* a, const unsigned* b) {
    asm volatile("mma.sync.aligned.m16n8k16.row.col.f32.bf16.bf16.f32 "
                 "{%0,%1,%2,%3}, {%4,%5,%6,%7}, {%8,%9}, {%0,%1,%2,%3};"
                 : "+f"(d[0]), "+f"(d[1]), "+f"(d[2]), "+f"(d[3])
                 : "r"(a[0]), "r"(a[1]), "r"(a[2]), "r"(a[3]), "r"(b[0]), "r"(b[1]));
}
__device__ __forceinline__ uint4 ldcg4(const uint4* p) {
    uint4 v;
    asm volatile("ld.global.cg.v4.u32 {%0,%1,%2,%3}, [%4];"
                 : "=r"(v.x), "=r"(v.y), "=r"(v.z), "=r"(v.w) : "l"(p));
    return v;
}
__device__ __forceinline__ unsigned ldacq(const unsigned* p) {
    unsigned v;
    asm volatile("ld.global.acquire.gpu.u32 %0, [%1];" : "=r"(v) : "l"(p));
    return v;
}

// ---------- setup ----------
__global__ void bias_kernel(const float* __restrict__ Wk, const float* __restrict__ bk,
                            const float* __restrict__ Wr, const float* __restrict__ br) {
    int j = blockIdx.x * blockDim.x + threadIdx.x;
    if (j < GG) g_bias[j] = bk[j] + br[j] + Wk[FF * GG + j] + Wr[HH * GG + j];
}
__global__ void init_state_kernel() {
    int i = blockIdx.x * blockDim.x + threadIdx.x;
    if (i < 4 * AFQ * 4) ((unsigned*)g_haf)[i] = 0u;
    if (i == 0) g_arrive = 0u;
}
__global__ void wct_kernel(const float* __restrict__ Wc) {
    int idx = blockIdx.x * blockDim.x + threadIdx.x;
    if (idx >= KKW * HH * HH) return;
    int kkidx = idx / HH, o = idx - kkidx * HH;
    int k = kkidx / HH, i = kkidx - k * HH;
    g_wct[idx] = Wc[(o * HH + i) * KKW + k];
}
// x -> fragment layout [t][half]
__global__ void xfrag_kernel(const float* __restrict__ x) {
    int half = blockIdx.x, t = blockIdx.y;
    unsigned* out = (unsigned*)(g_xaf + ((size_t)t * 2 + half) * XFQ);
    const float* xb = x + ((size_t)t * BB + half * 128) * FF;
    for (int e = threadIdx.x; e < 128 * 64; e += 256) {
        int r = e >> 6, k2 = e & 63;
        unsigned v = packbf(xb[r * FF + 2 * k2], xb[r * FF + 2 * k2 + 1]);
        int kk = k2 >> 3, tg = k2 & 3, k4 = (k2 >> 2) & 1;
        int u4 = kk * 256 + (r >> 4) * 32 + ((r & 7) << 2) + tg;
        int comp = (k4 << 1) | ((r >> 3) & 1);
        out[u4 * 4 + comp] = v;
    }
}

// ---------- persistent recurrence ----------
extern __shared__ unsigned dsm[];
__global__ __launch_bounds__(256, 1) void stage_persistent(
    const float* __restrict__ Wr, const float* __restrict__ Wk)
{
    uint4* BF4 = (uint4*)dsm;                        // Wr frags, conflict-free layout
    uint4* WX4 = (uint4*)(dsm + 6144);               // Wk frags
    float* xo_s = (float*)(dsm + 6144 + 2048);       // [128][XOS]
    const int tid = threadIdx.x, blk = blockIdx.x;
    const int half = blk & 1, slice = blk >> 1;
    const int b0 = half * 128, j0 = slice * JC;
    const int w = tid >> 5, lane = tid & 31, gq = lane >> 2, tg = lane & 3;
    const int m0 = w * 16;
    const int row = m0 + (lane >> 1);
    const int jh  = lane & 1;

    // ---- build packed Wr fragments, layout [kk][granule][lane][4u32] (conflict-free) ----
    for (int e = tid; e < 6144; e += 256) {
        int kk = e >> 8, lane2 = (e >> 3) & 31, j = e & 7;
        int gq2 = lane2 >> 2, tg2 = lane2 & 3;
        int k2 = kk * 8 + tg2 + 4 * (j & 1);
        int n = (j >> 1) * 8 + gq2;
        unsigned v = 0u;
        if (n < NCOL) {
            int c = gcol6(n, j0);
            v = packbf(Wr[(size_t)(2*k2) * GG + c], Wr[(size_t)(2*k2+1) * GG + c]);
        }
        dsm[kk * 256 + ((j >> 2) << 7) + lane2 * 4 + (j & 3)] = v;
    }
    // ---- Wk fragments, same layout (8 chunks) ----
    for (int e = tid; e < 2048; e += 256) {
        int kk = e >> 8, lane2 = (e >> 3) & 31, j = e & 7;
        int gq2 = lane2 >> 2, tg2 = lane2 & 3;
        int k2 = kk * 8 + tg2 + 4 * (j & 1);
        int n = (j >> 1) * 8 + gq2;
        unsigned v = 0u;
        if (n < NCOL) {
            int c = gcol6(n, j0);
            v = packbf(Wk[(size_t)(2*k2) * GG + c], Wk[(size_t)(2*k2+1) * GG + c]);
        }
        dsm[6144 + kk * 256 + ((j >> 2) << 7) + lane2 * 4 + (j & 3)] = v;
    }
    __syncthreads();

    float c_reg[3] = {0.0f, 0.0f, 0.0f};

    float xk6[6], xkg[12];
    {
        #pragma unroll
        for (int c = 0; c < 6; c++) xk6[c] = g_bias[c];
        #pragma unroll
        for (int q2 = 0; q2 < 3; q2++) {
            int jj = 3 * jh + q2;
            #pragma unroll
            for (int gc = 0; gc < 4; gc++)
                xkg[q2 * 4 + gc] = g_bias[6 + gc * HH + j0 + jj];
        }
    }

    const int kks = slice % NKK;   // staggered start chunk

    for (int t = 0; t < TT; t++) {
        const uint4* AF  = g_haf + (size_t)((t & 1) * 2 + half) * AFQ;
        unsigned*    AFn = (unsigned*)(g_haf + (size_t)(((t + 1) & 1) * 2 + half) * AFQ);
        const uint4* AX  = g_xaf + ((size_t)t * 2 + half) * XFQ;

        float acc[NT][4];
        #pragma unroll
        for (int nt = 0; nt < NT; nt++)
            #pragma unroll
            for (int q = 0; q < 4; q++) acc[nt][q] = 0.0f;

        const uint4* afp = AF + w * 32 + lane;
        const uint4* axp = AX + w * 32 + lane;

        // ---- x@Wk FIRST (independent of h(t); overlaps barrier slack) ----
        #pragma unroll
        for (int kk = 0; kk < NKX; kk++) {
            uint4 a = ldcg4(axp + kk * 256);
            uint4 p = WX4[kk * 64 + lane];
            uint4 q = WX4[kk * 64 + 32 + lane];
            unsigned af[4] = { a.x, a.y, a.z, a.w };
            unsigned bf0[2] = { p.x, p.y }, bf1[2] = { p.z, p.w };
            unsigned bf2[2] = { q.x, q.y }, bf3[2] = { q.z, q.w };
            mma16(acc[0], af, bf0);
            mma16(acc[1], af, bf1);
            mma16(acc[2], af, bf2);
            mma16(acc[3], af, bf3);
        }

        // ---- per-warp wait for all h(t) fragments ----
        {
            unsigned tgt = (unsigned)t * NBLK;
            if (lane == 0) {
                unsigned v;
                do { v = ldacq(&g_arrive); } while (v < tgt);
            }
            __syncwarp();
        }

        // ---- h@Wr, staggered chunk order ----
        #pragma unroll
        for (int i = 0; i < NKK; i++) {
            int kk = i + kks; if (kk >= NKK) kk -= NKK;
            uint4 a = ldcg4(afp + kk * 256);
            uint4 p = BF4[kk * 64 + lane];
            uint4 q = BF4[kk * 64 + 32 + lane];
            unsigned af[4] = { a.x, a.y, a.z, a.w };
            unsigned bf0[2] = { p.x, p.y }, bf1[2] = { p.z, p.w };
            unsigned bf2[2] = { q.x, q.y }, bf3[2] = { q.z, q.w };
            mma16(acc[0], af, bf0);
            mma16(acc[1], af, bf1);
            mma16(acc[2], af, bf2);
            mma16(acc[3], af, bf3);
        }

        // ---- xo to warp-private smem slice ----
        {
            int r = m0 + gq;
            #pragma unroll
            for (int nt = 0; nt < NT; nt++) {
                int cb = nt * 8 + 2 * tg;
                xo_s[r * XOS + cb]           = acc[nt][0];
                xo_s[r * XOS + cb + 1]       = acc[nt][1];
                xo_s[(r + 8) * XOS + cb]     = acc[nt][2];
                xo_s[(r + 8) * XOS + cb + 1] = acc[nt][3];
            }
        }
        __syncwarp();

        // ---- gates: warp-local, 2 lanes/row, 3 jj each ----
        {
            const float* xr = xo_s + row * XOS;
            float a0 = xr[0] + xk6[0], a1 = xr[1] + xk6[1], a2 = xr[2] + xk6[2];
            float m = fmaxf(a0, fmaxf(a1, a2));
            float e0 = __expf(a0 - m), e1 = __expf(a1 - m), e2 = __expf(a2 - m);
            float rs = __fdividef(1.0f, e0 + e1 + e2);
            float f0 = e0 * rs, f1 = (e0 + e1) * rs;
            float b0v = xr[3] + xk6[3], b1v = xr[4] + xk6[4], b2v = xr[5] + xk6[5];
            m = fmaxf(b0v, fmaxf(b1v, b2v));
            e0 = __expf(b0v - m); e1 = __expf(b1v - m); e2 = __expf(b2v - m);
            rs = __fdividef(1.0f, e0 + e1 + e2);
            float i1 = (e1 + e2) * rs, i2 = e2 * rs;
            float cd = 1.0f - (f0 + f1 + 1.0f) * (1.0f / 3.0f);
            const bool hist = (t >= TT - KKW);
            const int slot = t % KKW;
            float hv[3];
            #pragma unroll
            for (int q2 = 0; q2 < 3; q2++) {
                int jj = 3 * jh + q2;
                int lg = (j0 + jj) >> 7;
                float fm = (lg == 0) ? f0 : ((lg == 1) ? f1 : 1.0f);
                float im = (lg == 0) ? 1.0f : ((lg == 1) ? i1 : i2);
                float ov = fm * im;
                float fg = siga(xr[6 + jj]      + xkg[q2 * 4 + 0]);
                float ig = siga(xr[12 + jj]     + xkg[q2 * 4 + 1]);
                float og = siga(xr[18 + jj]     + xkg[q2 * 4 + 2]);
                float ci = tanha(xr[24 + jj]    + xkg[q2 * 4 + 3]);
                float cn = c_reg[q2] * (ov * fg + fm - ov) + ci * (ov * ig + im - ov);
                c_reg[q2] = cn;
                hv[q2] = og * tanha(cn);
            }
            float h3 = __shfl_xor_sync(0xFFFFFFFFu, hv[0], 1);
            const int r = row;
            auto put = [&](int c, unsigned v) {
                int kk = c >> 3, o = c & 7;
                int lane3 = ((r & 7) << 2) | (o & 3);
                int comp = ((o >> 2) << 1) | ((r >> 3) & 1);
                AFn[(((kk << 3) + (r >> 4)) * 32 + lane3) * 4 + comp] = v;
            };
            if (jh == 0) {
                put(3 * slice,     packbf(hv[0], hv[1]));
                put(3 * slice + 1, packbf(hv[2], h3));
            } else {
                put(3 * slice + 2, packbf(hv[1], hv[2]));
            }
            if (hist) {
                #pragma unroll
                for (int q2 = 0; q2 < 3; q2++)
                    g_hist_h[slot * BB * HH + (b0 + r) * HH + j0 + 3 * jh + q2] = hv[q2];
                if (jh == 0 && slice == 0)
                    g_hist_d[slot * BB + b0 + r] = cd;
            }
        }

        // ---- single block barrier, then flat arrive ----
        __syncthreads();
        if (tid == 0) {
            __threadfence();
            atomicAdd(&g_arrive, 1u);
        }
    }
}

// ---------- final head ----------
__global__ void dis_kernel() {
    int b = threadIdx.x;
    if (b >= BB) return;
    float cum = 0.0f, v[KKW];
    #pragma unroll
    for (int k = 0; k < KKW; k++) {
        cum += g_hist_d[((TT - KKW + k) % KKW) * BB + b];
        v[k] = cum;
    }
    float m = v[0];
    #pragma unroll
    for (int k = 1; k < KKW; k++) m = fmaxf(m, v[k]);
    float s = 0.0f;
    #pragma unroll
    for (int k = 0; k < KKW; k++) { v[k] = expf(v[k] - m); s += v[k]; }
    float inv = 1.0f / s;
    #pragma unroll
    for (int k = 0; k < KKW; k++) g_dis[b * KKW + k] = v[k] * inv;
}
__global__ void wh_kernel() {
    int idx = blockIdx.x * blockDim.x + threadIdx.x;
    if (idx >= BB * HH) return;
    int b = idx / HH;
    float acc = 0.0f;
    #pragma unroll
    for (int k = 0; k < KKW; k++) {
        float v = g_hist_h[((TT - KKW + k) % KKW) * BB * HH + idx] * g_dis[b * KKW + k];
        g_wh[k * BB * HH + idx] = v;
        acc += v;
    }
    g_M[idx] = acc * (1.0f / KKW);
}
__global__ __launch_bounds__(256) void conv_kernel(const float* __restrict__ bc) {
    __shared__ float Asm[16][65];
    __shared__ float Bsm[16][64];
    const int tx = threadIdx.x & 15, ty = threadIdx.x >> 4;
    const int b0 = blockIdx.y * 64, o0 = blockIdx.x * 64;
    float acc[4][4] = {};
    for (int kk0 = 0; kk0 < KKW * HH; kk0 += 16) {
        #pragma unroll
        for (int x2 = threadIdx.x; x2 < 1024; x2 += 256) {
            int bb = x2 >> 4, kk = x2 & 15;
            int kkidx = kk0 + kk, k = kkidx / HH, i = kkidx - k * HH;
            Asm[kk][bb] = g_wh[k * BB * HH + (b0 + bb) * HH + i];
        }
        #pragma unroll
        for (int x2 = threadIdx.x; x2 < 1024; x2 += 256) {
            int kk = x2 >> 6, oo = x2 & 63;
            Bsm[kk][oo] = g_wct[(size_t)(kk0 + kk) * HH + o0 + oo];
        }
        __syncthreads();
        #pragma unroll
        for (int kk = 0; kk < 16; kk++) {
            float av[4], bv[4];
            #pragma unroll
            for (int m = 0; m < 4; m++) av[m] = Asm[kk][ty * 4 + m];
            #pragma unroll
            for (int n = 0; n < 4; n++) bv[n] = Bsm[kk][tx * 4 + n];
            #pragma unroll
            for (int m = 0; m < 4; m++)
                #pragma unroll
                for (int n = 0; n < 4; n++) acc[m][n] += av[m] * bv[n];
        }
        __syncthreads();
    }
    #pragma unroll
    for (int m = 0; m < 4; m++)
        #pragma unroll
        for (int n = 0; n < 4; n++)
            g_conv[(b0 + ty * 4 + m) * HH + o0 + tx * 4 + n] = acc[m][n] + bc[o0 + tx * 4 + n];
}
__global__ void p_kernel(const float* __restrict__ Ws, const float* __restrict__ bs) {
    int b = blockIdx.x, s2 = threadIdx.x;
    float acc = bs[s2];
    for (int i = 0; i < HH; i++) acc += g_M[b * HH + i] * Ws[i * SS + s2];
    g_P[b * SS + s2] = fmaxf(acc, 0.0f);
}
__global__ void theme_kernel(const float* __restrict__ Wrs, const float* __restrict__ brs) {
    int b = blockIdx.x, o = threadIdx.x;
    float acc = brs[o];
    #pragma unroll 8
    for (int s2 = 0; s2 < SS; s2++) acc += g_P[b * SS + s2] * Wrs[s2 * HH + o];
    g_theme[b * HH + o] = sigmoidf(acc);
}
__global__ void out_kernel(const float* __restrict__ Wo, const float* __restrict__ bo,
                           float* __restrict__ out) {
    int b = blockIdx.x;
    __shared__ float red[128];
    const float* hfin = g_hist_h + ((TT - 1) % KKW) * BB * HH;
    float acc = 0.0f;
    for (int i = threadIdx.x; i < HH; i += 128) {
        float rnn = g_theme[b * HH + i] * g_conv[b * HH + i] + hfin[b * HH + i];
        acc += rnn * Wo[i];
    }
    red[threadIdx.x] = acc;
    __syncthreads();
    for (int s = 64; s > 0; s >>= 1) {
        if (threadIdx.x < s) red[threadIdx.x] += red[threadIdx.x + s];
        __syncthreads();
    }
    if (threadIdx.x == 0) out[b] = sigmoidf(red[0] + bo[0]);
}

// ---------- host ----------
extern "C" void kernel_launch(void* const* d_in, const int* in_sizes, int n_in,
                              void* d_out, int out_size)
{
    (void)in_sizes; (void)n_in; (void)out_size;
    const float* x   = (const float*)d_in[0];
    const float* Wk  = (const float*)d_in[1];
    const float* bk  = (const float*)d_in[2];
    const float* Wr  = (const float*)d_in[3];
    const float* br  = (const float*)d_in[4];
    const float* Ws  = (const float*)d_in[5];
    const float* bs  = (const float*)d_in[6];
    const float* Wrs = (const float*)d_in[7];
    const float* brs = (const float*)d_in[8];
    const float* Wc  = (const float*)d_in[9];
    const float* bc  = (const float*)d_in[10];
    const float* Wo  = (const float*)d_in[11];
    const float* bo  = (const float*)d_in[12];

    cudaFuncSetAttribute(stage_persistent, cudaFuncAttributeMaxDynamicSharedMemorySize, SMEM_BYTES);

    bias_kernel<<<(GG + 255) / 256, 256>>>(Wk, bk, Wr, br);
    init_state_kernel<<<(4 * AFQ * 4 + 255) / 256, 256>>>();
    wct_kernel<<<(KKW * HH * HH + 255) / 256, 256>>>(Wc);
    xfrag_kernel<<<dim3(2, TT), 256>>>(x);

    stage_persistent<<<NBLK, 256, SMEM_BYTES>>>(Wr, Wk);

    dis_kernel<<<1, 256>>>();
    wh_kernel<<<(BB * HH + 255) / 256, 256>>>();
    conv_kernel<<<dim3(HH / 64, BB / 64), 256>>>(bc);
    p_kernel<<<BB, SS>>>(Ws, bs);
    theme_kernel<<<BB, HH>>>(Wrs, brs);
    out_kernel<<<BB, 128>>>(Wo, bo, (float*)d_out);
}